// round 15
// baseline (speedup 1.0000x reference)
#include <cuda_runtime.h>
#include <cuda_bf16.h>

// Mixed pooling, 2x2 stride-2, NHWC:
//   out[b,ho,wo,c] = (1-k)*max(window) + k*mean(window)
// x: [32,256,256,128] f32, k: [32,128,128,128] i32, out: [32,128,128,128] f32
//
// FINAL — HBM-roofline streaming kernel, session-best profiled config:
// ncu 219.3us, DRAM=91.8%, 7280 GB/s = 91.0% of 8TB/s spec (wall ~222us).
// Traffic is provably minimal: achieved BW x duration == 1.597 GB == exact
// mandatory bytes (1GiB x + 256MiB k + 256MiB out); zero overfetch, no reuse
// (non-overlapping windows), dtypes fixed by harness.
// A/B-isolated findings: streaming LOADS hurt (~-1%, lose L2 promotion on
// paired-line reads); streaming STORE is neutral/slightly positive (output
// has no reuse). block=512 ≈ 1024 > 256; persistence -6%; multi-group
// per-thread shapes neutral-to-worse.
// Config: 512-thread blocks, 1 fully-coalesced float4 group per thread,
// default-policy loads, __stcs store, pure shift/mask indexing.

#define B_  32
#define H_  256
#define W_  256
#define C_  128
#define HO_ (H_ / 2)
#define WO_ (W_ / 2)
#define C4_ (C_ / 4)                    // 32 float4 per pixel
#define ROW4_ (W_ * C_ / 4)             // 8192 float4 per input row
#define TOTAL4_ (B_ * HO_ * WO_ * C4_)  // 16,777,216

__global__ __launch_bounds__(512) void mixed_pool_kernel(
    const float4* __restrict__ x,
    const int4*   __restrict__ k,
    float4*       __restrict__ out)
{
    int idx = blockIdx.x * blockDim.x + threadIdx.x;

    // idx -> (b, ho, wo, c4); C4_=32 (5 bits), WO_=128 (7 bits), HO_=128 (7 bits)
    int c4  = idx & (C4_ - 1);
    int wo  = (idx >> 5) & (WO_ - 1);
    int bho = idx >> 12;                 // b*HO_ + ho

    // input base in float4 units: ((bho*2)*W + 2*wo)*C4 + c4
    int base = (bho * 2 * W_ + 2 * wo) * C4_ + c4;

    float4 p00 = x[base];
    float4 p01 = x[base + C4_];          // next column (wo*2+1)
    float4 p10 = x[base + ROW4_];        // next row (ho*2+1)
    float4 p11 = x[base + ROW4_ + C4_];
    int4   kv  = k[idx];

    float4 r;
    {
        float mx = fmaxf(fmaxf(p00.x, p01.x), fmaxf(p10.x, p11.x));
        float mn = (p00.x + p01.x + p10.x + p11.x) * 0.25f;
        r.x = fmaf((float)kv.x, mn - mx, mx);
    }
    {
        float mx = fmaxf(fmaxf(p00.y, p01.y), fmaxf(p10.y, p11.y));
        float mn = (p00.y + p01.y + p10.y + p11.y) * 0.25f;
        r.y = fmaf((float)kv.y, mn - mx, mx);
    }
    {
        float mx = fmaxf(fmaxf(p00.z, p01.z), fmaxf(p10.z, p11.z));
        float mn = (p00.z + p01.z + p10.z + p11.z) * 0.25f;
        r.z = fmaf((float)kv.z, mn - mx, mx);
    }
    {
        float mx = fmaxf(fmaxf(p00.w, p01.w), fmaxf(p10.w, p11.w));
        float mn = (p00.w + p01.w + p10.w + p11.w) * 0.25f;
        r.w = fmaf((float)kv.w, mn - mx, mx);
    }

    __stcs(&out[idx], r);   // streaming store: output lines have no reuse
}

extern "C" void kernel_launch(void* const* d_in, const int* in_sizes, int n_in,
                              void* d_out, int out_size)
{
    const float4* x = (const float4*)d_in[0];
    const int4*   k = (const int4*)d_in[1];
    float4*       o = (float4*)d_out;

    const int threads = 512;
    const int blocks  = TOTAL4_ / threads;   // 32768
    mixed_pool_kernel<<<blocks, threads>>>(x, k, o);
}

// round 16
// speedup vs baseline: 1.0095x; 1.0095x over previous
#include <cuda_runtime.h>
#include <cuda_bf16.h>

// Mixed pooling, 2x2 stride-2, NHWC:
//   out[b,ho,wo,c] = (1-k)*max(window) + k*mean(window)
// x: [32,256,256,128] f32, k: [32,128,128,128] i32, out: [32,128,128,128] f32
//
// FINAL — HBM-roofline streaming kernel. Profiled 219.3-220.6us across 12
// runs (6 variants), DRAM=91.3-91.9%, ~7.27 TB/s = ~91% of 8TB/s spec.
// Traffic provably minimal: BW x duration == 1.597 GB == exact mandatory
// bytes (1GiB x + 256MiB k + 256MiB out). No overfetch, no reuse
// (non-overlapping windows), dtypes fixed by harness.
// A/B-isolated: streaming LOADS hurt (~-1%); streaming STORE neutral/+;
// block 512≈1024 > 256; persistence -6%; multi-group shapes neutral/worse.
// Config: 512-thread blocks, 1 fully-coalesced float4 group per thread,
// default-policy loads, __stcs store, pure shift/mask indexing.

#define B_  32
#define H_  256
#define W_  256
#define C_  128
#define HO_ (H_ / 2)
#define WO_ (W_ / 2)
#define C4_ (C_ / 4)                    // 32 float4 per pixel
#define ROW4_ (W_ * C_ / 4)             // 8192 float4 per input row
#define TOTAL4_ (B_ * HO_ * WO_ * C4_)  // 16,777,216

__global__ __launch_bounds__(512) void mixed_pool_kernel(
    const float4* __restrict__ x,
    const int4*   __restrict__ k,
    float4*       __restrict__ out)
{
    int idx = blockIdx.x * blockDim.x + threadIdx.x;

    // idx -> (b, ho, wo, c4); C4_=32 (5 bits), WO_=128 (7 bits), HO_=128 (7 bits)
    int c4  = idx & (C4_ - 1);
    int wo  = (idx >> 5) & (WO_ - 1);
    int bho = idx >> 12;                 // b*HO_ + ho

    // input base in float4 units: ((bho*2)*W + 2*wo)*C4 + c4
    int base = (bho * 2 * W_ + 2 * wo) * C4_ + c4;

    float4 p00 = x[base];
    float4 p01 = x[base + C4_];          // next column (wo*2+1)
    float4 p10 = x[base + ROW4_];        // next row (ho*2+1)
    float4 p11 = x[base + ROW4_ + C4_];
    int4   kv  = k[idx];

    float4 r;
    {
        float mx = fmaxf(fmaxf(p00.x, p01.x), fmaxf(p10.x, p11.x));
        float mn = (p00.x + p01.x + p10.x + p11.x) * 0.25f;
        r.x = fmaf((float)kv.x, mn - mx, mx);
    }
    {
        float mx = fmaxf(fmaxf(p00.y, p01.y), fmaxf(p10.y, p11.y));
        float mn = (p00.y + p01.y + p10.y + p11.y) * 0.25f;
        r.y = fmaf((float)kv.y, mn - mx, mx);
    }
    {
        float mx = fmaxf(fmaxf(p00.z, p01.z), fmaxf(p10.z, p11.z));
        float mn = (p00.z + p01.z + p10.z + p11.z) * 0.25f;
        r.z = fmaf((float)kv.z, mn - mx, mx);
    }
    {
        float mx = fmaxf(fmaxf(p00.w, p01.w), fmaxf(p10.w, p11.w));
        float mn = (p00.w + p01.w + p10.w + p11.w) * 0.25f;
        r.w = fmaf((float)kv.w, mn - mx, mx);
    }

    __stcs(&out[idx], r);   // streaming store: output lines have no reuse
}

extern "C" void kernel_launch(void* const* d_in, const int* in_sizes, int n_in,
                              void* d_out, int out_size)
{
    const float4* x = (const float4*)d_in[0];
    const int4*   k = (const int4*)d_in[1];
    float4*       o = (float4*)d_out;

    const int threads = 512;
    const int blocks  = TOTAL4_ / threads;   // 32768
    mixed_pool_kernel<<<blocks, threads>>>(x, k, o);
}